// round 14
// baseline (speedup 1.0000x reference)
#include <cuda_runtime.h>

#define BATCH   262144
#define T_STEPS 20
#define BETAF   0.9f
#define THRESHF 1.0f

using u32 = unsigned int;
using u64 = unsigned long long;

__device__ __forceinline__ u64 pack2(float lo, float hi) {
    u64 r; asm("mov.b64 %0, {%1, %2};" : "=l"(r) : "f"(lo), "f"(hi)); return r;
}
__device__ __forceinline__ void unpack2(u64 v, float &lo, float &hi) {
    asm("mov.b64 {%0, %1}, %2;" : "=f"(lo), "=f"(hi) : "l"(v));
}
__device__ __forceinline__ void unpacki(u64 v, u32 &lo, u32 &hi) {
    asm("mov.b64 {%0, %1}, %2;" : "=r"(lo), "=r"(hi) : "l"(v));
}
// Packed dual fp32 FMA (2 MACs / instruction on the fma pipe)
__device__ __forceinline__ u64 ffma2(u64 a, u64 b, u64 c) {
    u64 d; asm("fma.rn.f32x2 %0, %1, %2, %3;" : "=l"(d) : "l"(a), "l"(b), "l"(c)); return d;
}

#define ONE2 0x3F8000003F800000ull

// ---- static smem weights, half-contiguous (warp-uniform addressing) ----
// layout [h][i][p]: w[(h*NIN + i)*P2 + p] = (W[h*2*P2 + 2p][i], W[...+1][i])
__shared__ u64 sW1[2 * 10 * 16];  // 10 -> 64, P2=16
__shared__ u64 sW2[2 * 64 * 8];   // 64 -> 32, P2=8
__shared__ u64 sW3[2 * 32 * 8];   // 32 -> 32, P2=8
__shared__ u64 sW4[2 * 32 * 4];   // 32 -> 16, P2=4
__shared__ u64 sW5[2 * 16 * 2];   // 16 -> 6 (padded to 8), P2=2
// spike exchange: per region [2 groups][32 lanes][2 halves] u32
__shared__ u32 spk[4 * 2 * 32 * 2];

__device__ __forceinline__ void stage(u64* dst, const float* __restrict__ W,
                                      int NIN, int NOUT, int P2, int tid) {
    int total = 2 * NIN * P2;
    for (int idx = tid; idx < total; idx += 128) {
        int h = idx / (NIN * P2);
        int r = idx % (NIN * P2);
        int i = r / P2, p = r % P2;
        int j0 = h * (2 * P2) + 2 * p;
        float a = (j0     < NOUT) ? W[j0 * NIN + i]       : 0.0f;
        float b = (j0 + 1 < NOUT) ? W[(j0 + 1) * NIN + i] : 0.0f;
        dst[idx] = pack2(a, b);
    }
}

// LIF for one output pair; returns 2-bit spike mask. Same formula/order as rounds 1-13.
__device__ __forceinline__ u32 lif_pair(u64 acc, float &mA, float &mB) {
    float a0, a1; unpack2(acc, a0, a1);
    float r0 = mA > THRESHF ? THRESHF : 0.0f;
    float r1 = mB > THRESHF ? THRESHF : 0.0f;
    mA = fmaf(BETAF, mA, a0 - r0);
    mB = fmaf(BETAF, mB, a1 - r1);
    u32 m = 0;
    if (mA > THRESHF) m |= 1u;
    if (mB > THRESHF) m |= 2u;
    return m;
}

__global__ __launch_bounds__(128, 3) void lif_kernel(
    const float* __restrict__ x,
    const float* __restrict__ W1, const float* __restrict__ W2,
    const float* __restrict__ W3, const float* __restrict__ W4,
    const float* __restrict__ W5, float* __restrict__ out)
{
    const int tid = threadIdx.x;
    stage(sW1, W1, 10, 64, 16, tid);
    stage(sW2, W2, 64, 32,  8, tid);
    stage(sW3, W3, 32, 32,  8, tid);
    stage(sW4, W4, 32, 16,  4, tid);
    stage(sW5, W5, 16,  6,  2, tid);
    __syncthreads();

    const int wq   = tid >> 5;          // warp id
    const int g    = wq >> 1;           // element group (0: elems 0..31, 1: 32..63)
    const int h    = wq & 1;            // half of every layer's outputs
    const int lane = tid & 31;
    const size_t e = (size_t)blockIdx.x * 64 + g * 32 + lane;   // one element per lane
    const int bar  = g + 1;             // named barrier per 64-thread group

    const u64* w1 = sW1 + h * (10 * 16);
    const u64* w2 = sW2 + h * (64 * 8);
    const u64* w3 = sW3 + h * (32 * 8);
    const u64* w4 = sW4 + h * (32 * 4);
    const u64* w5 = sW5 + h * (16 * 2);
    // exchange slots: region base + g*64 + lane*2 + h (reader does LDS.64 at lane*2)
    u32* sp1 = spk + 0   + g * 64;
    u32* sp2 = spk + 128 + g * 64;
    u32* sp3 = spk + 256 + g * 64;
    u32* sp4 = spk + 384 + g * 64;

    // membrane state: half of every layer (76 floats)
    float m1[32], m2[16], m3[16], m4[8], m5[4];
#pragma unroll
    for (int k = 0; k < 32; ++k) m1[k] = 0.f;
#pragma unroll
    for (int k = 0; k < 16; ++k) { m2[k] = 0.f; m3[k] = 0.f; }
#pragma unroll
    for (int k = 0; k < 8; ++k)  m4[k] = 0.f;
#pragma unroll
    for (int k = 0; k < 4; ++k)  m5[k] = 0.f;

#pragma unroll 1
    for (int t = 0; t < T_STEPS; ++t) {
        // ================= Layer 1: 10 -> 64 (16 pairs per half) ================
        const float2* xp = (const float2*)(x + ((size_t)t * BATCH + e) * 10);
        float2 xv[5];
#pragma unroll
        for (int i = 0; i < 5; ++i) xv[i] = xp[i];

        u64 acc1[16];
#pragma unroll
        for (int p = 0; p < 16; ++p) acc1[p] = 0ull;
#pragma unroll
        for (int i = 0; i < 10; ++i) {
            const ulonglong2* wp = (const ulonglong2*)(w1 + i * 16);
            float xf = (i & 1) ? xv[i >> 1].y : xv[i >> 1].x;
            u64 xd = pack2(xf, xf);
#pragma unroll
            for (int p2 = 0; p2 < 8; ++p2) {
                ulonglong2 w = wp[p2];
                acc1[2 * p2]     = ffma2(xd, w.x, acc1[2 * p2]);
                acc1[2 * p2 + 1] = ffma2(xd, w.y, acc1[2 * p2 + 1]);
            }
        }
        {
            u32 mk = 0;
#pragma unroll
            for (int p = 0; p < 16; ++p)
                mk |= lif_pair(acc1[p], m1[2 * p], m1[2 * p + 1]) << (2 * p);
            sp1[lane * 2 + h] = mk;    // half0 -> L1 outs 0..31, half1 -> 32..63
        }
        // prefetch next step's x into L2 (40B per thread, contiguous across lanes)
        {
            size_t tn = (t + 1 < T_STEPS) ? (size_t)(t + 1) : (size_t)t;
            const char* nx = (const char*)(x + (tn * BATCH + e) * 10);
            asm volatile("prefetch.global.L2 [%0];" :: "l"(nx));
            asm volatile("prefetch.global.L2 [%0];" :: "l"(nx + 39));
        }
        asm volatile("bar.sync %0, %1;" :: "r"(bar), "r"(64) : "memory");
        u32 lo, hi;
        unpacki(*(const u64*)(sp1 + lane * 2), lo, hi);

        // ================= Layer 2: 64 -> 32 (8 pairs per half) =================
        u64 acc2[8];
#pragma unroll
        for (int p = 0; p < 8; ++p) acc2[p] = 0ull;
#pragma unroll
        for (int i = 0; i < 64; ++i) {
            const ulonglong2* wp = (const ulonglong2*)(w2 + i * 8);
            u32 bit = 1u << (i & 31);
            u64 hh = (((i < 32) ? lo : hi) & bit) ? ONE2 : 0ull;
            ulonglong2 wa = wp[0], wb = wp[1], wc = wp[2], wd = wp[3];
            acc2[0] = ffma2(hh, wa.x, acc2[0]);
            acc2[1] = ffma2(hh, wa.y, acc2[1]);
            acc2[2] = ffma2(hh, wb.x, acc2[2]);
            acc2[3] = ffma2(hh, wb.y, acc2[3]);
            acc2[4] = ffma2(hh, wc.x, acc2[4]);
            acc2[5] = ffma2(hh, wc.y, acc2[5]);
            acc2[6] = ffma2(hh, wd.x, acc2[6]);
            acc2[7] = ffma2(hh, wd.y, acc2[7]);
        }
        {
            u32 mk = 0;
#pragma unroll
            for (int p = 0; p < 8; ++p)
                mk |= lif_pair(acc2[p], m2[2 * p], m2[2 * p + 1]) << (2 * p);
            sp2[lane * 2 + h] = mk << (h * 16);
        }
        asm volatile("bar.sync %0, %1;" :: "r"(bar), "r"(64) : "memory");
        u32 f2;
        { u32 a, b; unpacki(*(const u64*)(sp2 + lane * 2), a, b); f2 = a | b; }

        // ================= Layer 3: 32 -> 32 (8 pairs per half) =================
        u64 acc3[8];
#pragma unroll
        for (int p = 0; p < 8; ++p) acc3[p] = 0ull;
#pragma unroll
        for (int i = 0; i < 32; ++i) {
            const ulonglong2* wp = (const ulonglong2*)(w3 + i * 8);
            u64 hh = (f2 & (1u << i)) ? ONE2 : 0ull;
            ulonglong2 wa = wp[0], wb = wp[1], wc = wp[2], wd = wp[3];
            acc3[0] = ffma2(hh, wa.x, acc3[0]);
            acc3[1] = ffma2(hh, wa.y, acc3[1]);
            acc3[2] = ffma2(hh, wb.x, acc3[2]);
            acc3[3] = ffma2(hh, wb.y, acc3[3]);
            acc3[4] = ffma2(hh, wc.x, acc3[4]);
            acc3[5] = ffma2(hh, wc.y, acc3[5]);
            acc3[6] = ffma2(hh, wd.x, acc3[6]);
            acc3[7] = ffma2(hh, wd.y, acc3[7]);
        }
        {
            u32 mk = 0;
#pragma unroll
            for (int p = 0; p < 8; ++p)
                mk |= lif_pair(acc3[p], m3[2 * p], m3[2 * p + 1]) << (2 * p);
            sp3[lane * 2 + h] = mk << (h * 16);
        }
        asm volatile("bar.sync %0, %1;" :: "r"(bar), "r"(64) : "memory");
        u32 f3;
        { u32 a, b; unpacki(*(const u64*)(sp3 + lane * 2), a, b); f3 = a | b; }

        // ================= Layer 4: 32 -> 16 (4 pairs per half) =================
        u64 acc4[4];
#pragma unroll
        for (int p = 0; p < 4; ++p) acc4[p] = 0ull;
#pragma unroll
        for (int i = 0; i < 32; ++i) {
            const ulonglong2* wp = (const ulonglong2*)(w4 + i * 4);
            u64 hh = (f3 & (1u << i)) ? ONE2 : 0ull;
            ulonglong2 wa = wp[0], wb = wp[1];
            acc4[0] = ffma2(hh, wa.x, acc4[0]);
            acc4[1] = ffma2(hh, wa.y, acc4[1]);
            acc4[2] = ffma2(hh, wb.x, acc4[2]);
            acc4[3] = ffma2(hh, wb.y, acc4[3]);
        }
        {
            u32 mk = 0;
#pragma unroll
            for (int p = 0; p < 4; ++p)
                mk |= lif_pair(acc4[p], m4[2 * p], m4[2 * p + 1]) << (2 * p);
            sp4[lane * 2 + h] = mk << (h * 8);
        }
        asm volatile("bar.sync %0, %1;" :: "r"(bar), "r"(64) : "memory");
        u32 f4;
        { u32 a, b; unpacki(*(const u64*)(sp4 + lane * 2), a, b); f4 = a | b; }

        // ================= Layer 5: 16 -> 6 (padded to 8; 2 pairs per half) ======
        u64 acc5[2];
        acc5[0] = 0ull; acc5[1] = 0ull;
#pragma unroll
        for (int i = 0; i < 16; ++i) {
            const ulonglong2* wp = (const ulonglong2*)(w5 + i * 2);
            u64 hh = (f4 & (1u << i)) ? ONE2 : 0ull;
            ulonglong2 wa = wp[0];
            acc5[0] = ffma2(hh, wa.x, acc5[0]);
            acc5[1] = ffma2(hh, wa.y, acc5[1]);
        }
        {
            float s[4];
#pragma unroll
            for (int p = 0; p < 2; ++p) {
                float a0, a1; unpack2(acc5[p], a0, a1);
                float r0 = m5[2 * p]     > THRESHF ? THRESHF : 0.0f;
                float r1 = m5[2 * p + 1] > THRESHF ? THRESHF : 0.0f;
                float mm0 = fmaf(BETAF, m5[2 * p],     a0 - r0);
                float mm1 = fmaf(BETAF, m5[2 * p + 1], a1 - r1);
                m5[2 * p] = mm0; m5[2 * p + 1] = mm1;
                s[2 * p]     = mm0 > THRESHF ? 1.0f : 0.0f;
                s[2 * p + 1] = mm1 > THRESHF ? 1.0f : 0.0f;
            }
            // out[t, e, 0:6]: half0 -> neurons 0..3, half1 -> 4..5
            float* op = out + ((size_t)t * BATCH + e) * 6;
            if (!h) {
                *(float2*)(op)     = make_float2(s[0], s[1]);
                *(float2*)(op + 2) = make_float2(s[2], s[3]);
            } else {
                *(float2*)(op + 4) = make_float2(s[0], s[1]);
            }
        }
    }
}

extern "C" void kernel_launch(void* const* d_in, const int* in_sizes, int n_in,
                              void* d_out, int out_size) {
    const float *x = nullptr, *W1 = nullptr, *W2 = nullptr, *W3 = nullptr,
                *W4 = nullptr, *W5 = nullptr;
    for (int i = 0; i < n_in; ++i) {
        const float* p = (const float*)d_in[i];
        switch (in_sizes[i]) {
            case 52428800: x  = p; break;  // (20, 262144, 10)
            case 640:      W1 = p; break;  // (64, 10)
            case 2048:     W2 = p; break;  // (32, 64)
            case 1024:     W3 = p; break;  // (32, 32)
            case 512:      W4 = p; break;  // (16, 32)
            case 96:       W5 = p; break;  // (6, 16)
            default: break;
        }
    }
    float* out = (float*)d_out;
    // 4 warps per block: 2 groups x 2 output-halves; 64 elements per block (1/lane)
    lif_kernel<<<BATCH / 64, 128>>>(x, W1, W2, W3, W4, W5, out);
}

// round 15
// speedup vs baseline: 1.2230x; 1.2230x over previous
#include <cuda_runtime.h>

#define BATCH   262144
#define T_STEPS 20
#define BETAF   0.9f
#define THRESHF 1.0f

using u32 = unsigned int;
using u64 = unsigned long long;

__device__ __forceinline__ u64 pack2(float lo, float hi) {
    u64 r; asm("mov.b64 %0, {%1, %2};" : "=l"(r) : "f"(lo), "f"(hi)); return r;
}
__device__ __forceinline__ void unpack2(u64 v, float &lo, float &hi) {
    asm("mov.b64 {%0, %1}, %2;" : "=f"(lo), "=f"(hi) : "l"(v));
}
__device__ __forceinline__ u64 packi(u32 lo, u32 hi) {
    u64 r; asm("mov.b64 %0, {%1, %2};" : "=l"(r) : "r"(lo), "r"(hi)); return r;
}
__device__ __forceinline__ void unpacki(u64 v, u32 &lo, u32 &hi) {
    asm("mov.b64 {%0, %1}, %2;" : "=r"(lo), "=r"(hi) : "l"(v));
}
// Packed dual fp32 FMA (2 MACs / instruction on the fma pipe)
__device__ __forceinline__ u64 ffma2(u64 a, u64 b, u64 c) {
    u64 d; asm("fma.rn.f32x2 %0, %1, %2, %3;" : "=l"(d) : "l"(a), "l"(b), "l"(c)); return d;
}

#define ONE2 0x3F8000003F800000ull

// ---- static smem weights, quarter-contiguous (warp-uniform addressing) ----
__shared__ u64 sW1[4 * 10 * 8];  // 10 -> 64, P4=8
__shared__ u64 sW2[4 * 64 * 4];  // 64 -> 32, P4=4
__shared__ u64 sW3[4 * 32 * 4];  // 32 -> 32, P4=4
__shared__ u64 sW4[4 * 32 * 2];  // 32 -> 16, P4=2
__shared__ u64 sW5[4 * 16 * 1];  // 16 -> 6 (padded to 8), P4=1
// spike-mask exchange: [region][wq][lane][el0,el1] (u32 units; u64 accesses)
__shared__ u32 spk[4 * 4 * 32 * 2];

__device__ __forceinline__ void stage(u64* dst, const float* __restrict__ W,
                                      int NIN, int NOUT, int P4, int tid) {
    int total = 4 * NIN * P4;
    for (int idx = tid; idx < total; idx += 128) {
        int q = idx / (NIN * P4);
        int r = idx % (NIN * P4);
        int i = r / P4, p = r % P4;
        int j0 = q * (2 * P4) + 2 * p;
        float a = (j0     < NOUT) ? W[j0 * NIN + i]       : 0.0f;
        float b = (j0 + 1 < NOUT) ? W[(j0 + 1) * NIN + i] : 0.0f;
        dst[idx] = pack2(a, b);
    }
}

// LIF for one output pair; returns 2-bit spike mask. Same formula/order as rounds 1-14.
__device__ __forceinline__ u32 lif_pair(u64 acc, float &mA, float &mB) {
    float a0, a1; unpack2(acc, a0, a1);
    float r0 = mA > THRESHF ? THRESHF : 0.0f;
    float r1 = mB > THRESHF ? THRESHF : 0.0f;
    mA = fmaf(BETAF, mA, a0 - r0);
    mB = fmaf(BETAF, mB, a1 - r1);
    u32 m = 0;
    if (mA > THRESHF) m |= 1u;
    if (mB > THRESHF) m |= 2u;
    return m;
}

__global__ __launch_bounds__(128, 3) void lif_kernel(
    const float* __restrict__ x,
    const float* __restrict__ W1, const float* __restrict__ W2,
    const float* __restrict__ W3, const float* __restrict__ W4,
    const float* __restrict__ W5, float* __restrict__ out)
{
    const int tid = threadIdx.x;
    stage(sW1, W1, 10, 64, 8, tid);
    stage(sW2, W2, 64, 32, 4, tid);
    stage(sW3, W3, 32, 32, 4, tid);
    stage(sW4, W4, 32, 16, 2, tid);
    stage(sW5, W5, 16,  6, 1, tid);
    __syncthreads();

    const int wq   = tid >> 5;      // warp = quarter of every layer's outputs
    const int lane = tid & 31;
    const size_t eglob = (size_t)blockIdx.x * 64 + lane * 2;  // elements 2*lane, 2*lane+1

    const u64* w1 = sW1 + wq * (10 * 8);
    const u64* w2 = sW2 + wq * (64 * 4);
    const u64* w3 = sW3 + wq * (32 * 4);
    const u64* w4 = sW4 + wq * (32 * 2);
    const u64* w5 = sW5 + wq * 16;
    u32* sp1 = spk;           // each region: [4 wq][32 lane][2 el]
    u32* sp2 = spk + 256;
    u32* sp3 = spk + 512;
    u32* sp4 = spk + 768;
    const int myoff = wq * 64 + lane * 2;   // producer u32 offset (u64-aligned)

    // membrane state: quarter of every layer, E=2 elements (38 floats each)
    float m1[2][16], m2[2][8], m3[2][8], m4[2][4], m5[2][2];
#pragma unroll
    for (int el = 0; el < 2; ++el) {
#pragma unroll
        for (int k = 0; k < 16; ++k) m1[el][k] = 0.f;
#pragma unroll
        for (int k = 0; k < 8; ++k) { m2[el][k] = 0.f; m3[el][k] = 0.f; }
#pragma unroll
        for (int k = 0; k < 4; ++k)  m4[el][k] = 0.f;
#pragma unroll
        for (int k = 0; k < 2; ++k)  m5[el][k] = 0.f;
    }

#pragma unroll 1
    for (int t = 0; t < T_STEPS; ++t) {
        // ================= Layer 1: 10 -> 64 (8 pairs per warp) =================
        // i-outer so each weight LDS is shared across BOTH elements.
        float2 xv[2][5];
#pragma unroll
        for (int el = 0; el < 2; ++el) {
            const float2* xp = (const float2*)(x + ((size_t)t * BATCH + eglob + el) * 10);
#pragma unroll
            for (int i = 0; i < 5; ++i) xv[el][i] = xp[i];
        }
        u64 acc1[2][8];
#pragma unroll
        for (int el = 0; el < 2; ++el)
#pragma unroll
            for (int p = 0; p < 8; ++p) acc1[el][p] = 0ull;
#pragma unroll
        for (int i = 0; i < 10; ++i) {
            const ulonglong2* wp = (const ulonglong2*)(w1 + i * 8);
            ulonglong2 wa = wp[0], wb = wp[1], wc = wp[2], wd = wp[3];
#pragma unroll
            for (int el = 0; el < 2; ++el) {
                float xf = (i & 1) ? xv[el][i >> 1].y : xv[el][i >> 1].x;
                u64 xd = pack2(xf, xf);
                acc1[el][0] = ffma2(xd, wa.x, acc1[el][0]);
                acc1[el][1] = ffma2(xd, wa.y, acc1[el][1]);
                acc1[el][2] = ffma2(xd, wb.x, acc1[el][2]);
                acc1[el][3] = ffma2(xd, wb.y, acc1[el][3]);
                acc1[el][4] = ffma2(xd, wc.x, acc1[el][4]);
                acc1[el][5] = ffma2(xd, wc.y, acc1[el][5]);
                acc1[el][6] = ffma2(xd, wd.x, acc1[el][6]);
                acc1[el][7] = ffma2(xd, wd.y, acc1[el][7]);
            }
        }
        {
            u32 m16[2];
#pragma unroll
            for (int el = 0; el < 2; ++el) {
                u32 mk = 0;
#pragma unroll
                for (int p = 0; p < 8; ++p)
                    mk |= lif_pair(acc1[el][p], m1[el][2 * p], m1[el][2 * p + 1]) << (2 * p);
                m16[el] = mk;
            }
            // store both elements' pre-shifted words as one STS.64
            u32 s0 = (wq & 1) ? (m16[0] << 16) : m16[0];
            u32 s1 = (wq & 1) ? (m16[1] << 16) : m16[1];
            *(u64*)(sp1 + myoff) = packi(s0, s1);
        }
        // prefetch next step's x (80 contiguous bytes for both elements) into L2
        {
            size_t tn = (t + 1 < T_STEPS) ? (size_t)(t + 1) : (size_t)t;
            const char* nx = (const char*)(x + (tn * BATCH + eglob) * 10);
            asm volatile("prefetch.global.L2 [%0];" :: "l"(nx));
            asm volatile("prefetch.global.L2 [%0];" :: "l"(nx + 79));
        }
        __syncthreads();
        u32 lo[2], hi[2];
        {
            u64 v0 = *(const u64*)(sp1 + 0 * 64 + lane * 2);
            u64 v1 = *(const u64*)(sp1 + 1 * 64 + lane * 2);
            u64 v2 = *(const u64*)(sp1 + 2 * 64 + lane * 2);
            u64 v3 = *(const u64*)(sp1 + 3 * 64 + lane * 2);
            u64 vlo = v0 | v1, vhi = v2 | v3;
            unpacki(vlo, lo[0], lo[1]);   // L1 outputs 0..31 per element
            unpacki(vhi, hi[0], hi[1]);   // L1 outputs 32..63 per element
        }

        // ================= Layer 2: 64 -> 32 (4 pairs per warp) =================
        u64 acc2[2][4];
#pragma unroll
        for (int el = 0; el < 2; ++el)
#pragma unroll
            for (int p = 0; p < 4; ++p) acc2[el][p] = 0ull;
#pragma unroll
        for (int i = 0; i < 64; ++i) {
            const ulonglong2* wp = (const ulonglong2*)(w2 + i * 4);
            ulonglong2 wa = wp[0], wb = wp[1];
            u32 bit = 1u << (i & 31);
            u64 h0 = (((i < 32) ? lo[0] : hi[0]) & bit) ? ONE2 : 0ull;
            u64 h1 = (((i < 32) ? lo[1] : hi[1]) & bit) ? ONE2 : 0ull;
            acc2[0][0] = ffma2(h0, wa.x, acc2[0][0]);
            acc2[0][1] = ffma2(h0, wa.y, acc2[0][1]);
            acc2[0][2] = ffma2(h0, wb.x, acc2[0][2]);
            acc2[0][3] = ffma2(h0, wb.y, acc2[0][3]);
            acc2[1][0] = ffma2(h1, wa.x, acc2[1][0]);
            acc2[1][1] = ffma2(h1, wa.y, acc2[1][1]);
            acc2[1][2] = ffma2(h1, wb.x, acc2[1][2]);
            acc2[1][3] = ffma2(h1, wb.y, acc2[1][3]);
        }
        {
            u32 w0 = 0, w1m = 0;
#pragma unroll
            for (int p = 0; p < 4; ++p) {
                w0  |= lif_pair(acc2[0][p], m2[0][2 * p], m2[0][2 * p + 1]) << (2 * p);
                w1m |= lif_pair(acc2[1][p], m2[1][2 * p], m2[1][2 * p + 1]) << (2 * p);
            }
            *(u64*)(sp2 + myoff) = packi(w0 << (wq * 8), w1m << (wq * 8));
        }
        __syncthreads();
        u32 f2[2];
        {
            u64 v = (*(const u64*)(sp2 + 0 * 64 + lane * 2))
                  | (*(const u64*)(sp2 + 1 * 64 + lane * 2))
                  | (*(const u64*)(sp2 + 2 * 64 + lane * 2))
                  | (*(const u64*)(sp2 + 3 * 64 + lane * 2));
            unpacki(v, f2[0], f2[1]);
        }

        // ================= Layer 3: 32 -> 32 =================
        u64 acc3[2][4];
#pragma unroll
        for (int el = 0; el < 2; ++el)
#pragma unroll
            for (int p = 0; p < 4; ++p) acc3[el][p] = 0ull;
#pragma unroll
        for (int i = 0; i < 32; ++i) {
            const ulonglong2* wp = (const ulonglong2*)(w3 + i * 4);
            ulonglong2 wa = wp[0], wb = wp[1];
            u32 bit = 1u << i;
            u64 h0 = (f2[0] & bit) ? ONE2 : 0ull;
            u64 h1 = (f2[1] & bit) ? ONE2 : 0ull;
            acc3[0][0] = ffma2(h0, wa.x, acc3[0][0]);
            acc3[0][1] = ffma2(h0, wa.y, acc3[0][1]);
            acc3[0][2] = ffma2(h0, wb.x, acc3[0][2]);
            acc3[0][3] = ffma2(h0, wb.y, acc3[0][3]);
            acc3[1][0] = ffma2(h1, wa.x, acc3[1][0]);
            acc3[1][1] = ffma2(h1, wa.y, acc3[1][1]);
            acc3[1][2] = ffma2(h1, wb.x, acc3[1][2]);
            acc3[1][3] = ffma2(h1, wb.y, acc3[1][3]);
        }
        {
            u32 w0 = 0, w1m = 0;
#pragma unroll
            for (int p = 0; p < 4; ++p) {
                w0  |= lif_pair(acc3[0][p], m3[0][2 * p], m3[0][2 * p + 1]) << (2 * p);
                w1m |= lif_pair(acc3[1][p], m3[1][2 * p], m3[1][2 * p + 1]) << (2 * p);
            }
            *(u64*)(sp3 + myoff) = packi(w0 << (wq * 8), w1m << (wq * 8));
        }
        __syncthreads();
        u32 f3[2];
        {
            u64 v = (*(const u64*)(sp3 + 0 * 64 + lane * 2))
                  | (*(const u64*)(sp3 + 1 * 64 + lane * 2))
                  | (*(const u64*)(sp3 + 2 * 64 + lane * 2))
                  | (*(const u64*)(sp3 + 3 * 64 + lane * 2));
            unpacki(v, f3[0], f3[1]);
        }

        // ================= Layer 4: 32 -> 16 (2 pairs per warp) =================
        u64 acc4[2][2];
#pragma unroll
        for (int el = 0; el < 2; ++el) { acc4[el][0] = 0ull; acc4[el][1] = 0ull; }
#pragma unroll
        for (int i = 0; i < 32; ++i) {
            const ulonglong2* wp = (const ulonglong2*)(w4 + i * 2);
            ulonglong2 wa = wp[0];
            u32 bit = 1u << i;
            u64 h0 = (f3[0] & bit) ? ONE2 : 0ull;
            u64 h1 = (f3[1] & bit) ? ONE2 : 0ull;
            acc4[0][0] = ffma2(h0, wa.x, acc4[0][0]);
            acc4[0][1] = ffma2(h0, wa.y, acc4[0][1]);
            acc4[1][0] = ffma2(h1, wa.x, acc4[1][0]);
            acc4[1][1] = ffma2(h1, wa.y, acc4[1][1]);
        }
        {
            u32 w0  = lif_pair(acc4[0][0], m4[0][0], m4[0][1])
                    | (lif_pair(acc4[0][1], m4[0][2], m4[0][3]) << 2);
            u32 w1m = lif_pair(acc4[1][0], m4[1][0], m4[1][1])
                    | (lif_pair(acc4[1][1], m4[1][2], m4[1][3]) << 2);
            *(u64*)(sp4 + myoff) = packi(w0 << (wq * 4), w1m << (wq * 4));
        }
        __syncthreads();
        u32 f4[2];
        {
            u64 v = (*(const u64*)(sp4 + 0 * 64 + lane * 2))
                  | (*(const u64*)(sp4 + 1 * 64 + lane * 2))
                  | (*(const u64*)(sp4 + 2 * 64 + lane * 2))
                  | (*(const u64*)(sp4 + 3 * 64 + lane * 2));
            unpacki(v, f4[0], f4[1]);
        }

        // ================= Layer 5: 16 -> 6 (padded; 1 pair per warp) ============
        u64 acc5[2];
        acc5[0] = 0ull; acc5[1] = 0ull;
#pragma unroll
        for (int i = 0; i < 16; ++i) {
            u64 w = w5[i];
            u32 bit = 1u << i;
            u64 h0 = (f4[0] & bit) ? ONE2 : 0ull;
            u64 h1 = (f4[1] & bit) ? ONE2 : 0ull;
            acc5[0] = ffma2(h0, w, acc5[0]);
            acc5[1] = ffma2(h1, w, acc5[1]);
        }
#pragma unroll
        for (int el = 0; el < 2; ++el) {
            float a0, a1; unpack2(acc5[el], a0, a1);
            float r0 = m5[el][0] > THRESHF ? THRESHF : 0.0f;
            float r1 = m5[el][1] > THRESHF ? THRESHF : 0.0f;
            float mm0 = fmaf(BETAF, m5[el][0], a0 - r0);
            float mm1 = fmaf(BETAF, m5[el][1], a1 - r1);
            m5[el][0] = mm0; m5[el][1] = mm1;
            if (wq < 3) {
                float2 o;
                o.x = mm0 > THRESHF ? 1.0f : 0.0f;
                o.y = mm1 > THRESHF ? 1.0f : 0.0f;
                *(float2*)(out + ((size_t)t * BATCH + eglob + el) * 6 + wq * 2) = o;
            }
        }
    }
}

extern "C" void kernel_launch(void* const* d_in, const int* in_sizes, int n_in,
                              void* d_out, int out_size) {
    const float *x = nullptr, *W1 = nullptr, *W2 = nullptr, *W3 = nullptr,
                *W4 = nullptr, *W5 = nullptr;
    for (int i = 0; i < n_in; ++i) {
        const float* p = (const float*)d_in[i];
        switch (in_sizes[i]) {
            case 52428800: x  = p; break;  // (20, 262144, 10)
            case 640:      W1 = p; break;  // (64, 10)
            case 2048:     W2 = p; break;  // (32, 64)
            case 1024:     W3 = p; break;  // (32, 32)
            case 512:      W4 = p; break;  // (16, 32)
            case 96:       W5 = p; break;  // (6, 16)
            default: break;
        }
    }
    float* out = (float*)d_out;
    // 4 warps per block = 4 output-quarters; 32 lanes x E=2 -> 64 elements per block
    lif_kernel<<<BATCH / 64, 128>>>(x, W1, W2, W3, W4, W5, out);
}

// round 16
// speedup vs baseline: 1.2746x; 1.0422x over previous
#include <cuda_runtime.h>

#define BATCH   262144
#define T_STEPS 20
#define BETAF   0.9f
#define THRESHF 1.0f

using u32 = unsigned int;
using u64 = unsigned long long;

__device__ __forceinline__ u64 pack2(float lo, float hi) {
    u64 r; asm("mov.b64 %0, {%1, %2};" : "=l"(r) : "f"(lo), "f"(hi)); return r;
}
__device__ __forceinline__ void unpack2(u64 v, float &lo, float &hi) {
    asm("mov.b64 {%0, %1}, %2;" : "=f"(lo), "=f"(hi) : "l"(v));
}
__device__ __forceinline__ u64 packi(u32 lo, u32 hi) {
    u64 r; asm("mov.b64 %0, {%1, %2};" : "=l"(r) : "r"(lo), "r"(hi)); return r;
}
__device__ __forceinline__ void unpacki(u64 v, u32 &lo, u32 &hi) {
    asm("mov.b64 {%0, %1}, %2;" : "=r"(lo), "=r"(hi) : "l"(v));
}
// Packed dual fp32 FMA (2 MACs / instruction on the fma pipe)
__device__ __forceinline__ u64 ffma2(u64 a, u64 b, u64 c) {
    u64 d; asm("fma.rn.f32x2 %0, %1, %2, %3;" : "=l"(d) : "l"(a), "l"(b), "l"(c)); return d;
}

#define ONE2 0x3F8000003F800000ull

// ---- static smem weights, quarter-contiguous (warp-uniform addressing) ----
__shared__ u64 sW1[4 * 10 * 8];  // 10 -> 64, P4=8
__shared__ u64 sW2[4 * 64 * 4];  // 64 -> 32, P4=4
__shared__ u64 sW3[4 * 32 * 4];  // 32 -> 32, P4=4
__shared__ u64 sW4[4 * 32 * 2];  // 32 -> 16, P4=2
__shared__ u64 sW5[4 * 16 * 1];  // 16 -> 6 (padded to 8), P4=1
// spike-mask exchange: [region][wq][lane][el0,el1] (u32 units; u64 accesses)
__shared__ u32 spk[4 * 4 * 32 * 2];

__device__ __forceinline__ void stage(u64* dst, const float* __restrict__ W,
                                      int NIN, int NOUT, int P4, int tid) {
    int total = 4 * NIN * P4;
    for (int idx = tid; idx < total; idx += 128) {
        int q = idx / (NIN * P4);
        int r = idx % (NIN * P4);
        int i = r / P4, p = r % P4;
        int j0 = q * (2 * P4) + 2 * p;
        float a = (j0     < NOUT) ? W[j0 * NIN + i]       : 0.0f;
        float b = (j0 + 1 < NOUT) ? W[(j0 + 1) * NIN + i] : 0.0f;
        dst[idx] = pack2(a, b);
    }
}

// LIF for one output pair; returns 2-bit spike mask. Same formula/order as rounds 1-15.
__device__ __forceinline__ u32 lif_pair(u64 acc, float &mA, float &mB) {
    float a0, a1; unpack2(acc, a0, a1);
    float r0 = mA > THRESHF ? THRESHF : 0.0f;
    float r1 = mB > THRESHF ? THRESHF : 0.0f;
    mA = fmaf(BETAF, mA, a0 - r0);
    mB = fmaf(BETAF, mB, a1 - r1);
    u32 m = 0;
    if (mA > THRESHF) m |= 1u;
    if (mB > THRESHF) m |= 2u;
    return m;
}

// Layer-1 compute for step ts: x load, 8 pairs per quarter for E=2 elements,
// LIF update of m1, pre-shifted mask STS into sp1. (i-outer: weight LDS shared
// across both elements.) Identical arithmetic/order to rounds 11/15.
__device__ __forceinline__ void l1_step(
    const float* __restrict__ x, int ts, size_t eglob,
    const u64* __restrict__ w1, float (&m1)[2][16],
    u32* sp1, int myoff, int wq)
{
    float2 xv[2][5];
#pragma unroll
    for (int el = 0; el < 2; ++el) {
        const float2* xp = (const float2*)(x + ((size_t)ts * BATCH + eglob + el) * 10);
#pragma unroll
        for (int i = 0; i < 5; ++i) xv[el][i] = xp[i];
    }
    u64 acc1[2][8];
#pragma unroll
    for (int el = 0; el < 2; ++el)
#pragma unroll
        for (int p = 0; p < 8; ++p) acc1[el][p] = 0ull;
#pragma unroll
    for (int i = 0; i < 10; ++i) {
        const ulonglong2* wp = (const ulonglong2*)(w1 + i * 8);
        ulonglong2 wa = wp[0], wb = wp[1], wc = wp[2], wd = wp[3];
#pragma unroll
        for (int el = 0; el < 2; ++el) {
            float xf = (i & 1) ? xv[el][i >> 1].y : xv[el][i >> 1].x;
            u64 xd = pack2(xf, xf);
            acc1[el][0] = ffma2(xd, wa.x, acc1[el][0]);
            acc1[el][1] = ffma2(xd, wa.y, acc1[el][1]);
            acc1[el][2] = ffma2(xd, wb.x, acc1[el][2]);
            acc1[el][3] = ffma2(xd, wb.y, acc1[el][3]);
            acc1[el][4] = ffma2(xd, wc.x, acc1[el][4]);
            acc1[el][5] = ffma2(xd, wc.y, acc1[el][5]);
            acc1[el][6] = ffma2(xd, wd.x, acc1[el][6]);
            acc1[el][7] = ffma2(xd, wd.y, acc1[el][7]);
        }
    }
    u32 m16[2];
#pragma unroll
    for (int el = 0; el < 2; ++el) {
        u32 mk = 0;
#pragma unroll
        for (int p = 0; p < 8; ++p)
            mk |= lif_pair(acc1[el][p], m1[el][2 * p], m1[el][2 * p + 1]) << (2 * p);
        m16[el] = mk;
    }
    u32 s0 = (wq & 1) ? (m16[0] << 16) : m16[0];
    u32 s1 = (wq & 1) ? (m16[1] << 16) : m16[1];
    *(u64*)(sp1 + myoff) = packi(s0, s1);
    // prefetch the step AFTER ts into L2 (80 contiguous bytes)
    {
        size_t tn = (ts + 1 < T_STEPS) ? (size_t)(ts + 1) : (size_t)ts;
        const char* nx = (const char*)(x + (tn * BATCH + eglob) * 10);
        asm volatile("prefetch.global.L2 [%0];" :: "l"(nx));
        asm volatile("prefetch.global.L2 [%0];" :: "l"(nx + 79));
    }
}

__global__ __launch_bounds__(128, 3) void lif_kernel(
    const float* __restrict__ x,
    const float* __restrict__ W1, const float* __restrict__ W2,
    const float* __restrict__ W3, const float* __restrict__ W4,
    const float* __restrict__ W5, float* __restrict__ out)
{
    const int tid = threadIdx.x;
    stage(sW1, W1, 10, 64, 8, tid);
    stage(sW2, W2, 64, 32, 4, tid);
    stage(sW3, W3, 32, 32, 4, tid);
    stage(sW4, W4, 32, 16, 2, tid);
    stage(sW5, W5, 16,  6, 1, tid);

    const int wq   = tid >> 5;      // warp = quarter of every layer's outputs
    const int lane = tid & 31;
    const size_t eglob = (size_t)blockIdx.x * 64 + lane * 2;  // elements 2*lane, 2*lane+1

    const u64* w1 = sW1 + wq * (10 * 8);
    const u64* w2 = sW2 + wq * (64 * 4);
    const u64* w3 = sW3 + wq * (32 * 4);
    const u64* w4 = sW4 + wq * (32 * 2);
    const u64* w5 = sW5 + wq * 16;
    u32* sp1 = spk;           // each region: [4 wq][32 lane][2 el]
    u32* sp2 = spk + 256;
    u32* sp3 = spk + 512;
    u32* sp4 = spk + 768;
    const int myoff = wq * 64 + lane * 2;   // producer u32 offset (u64-aligned)

    // membrane state: quarter of every layer, E=2 elements (38 floats each)
    float m1[2][16], m2[2][8], m3[2][8], m4[2][4], m5[2][2];
#pragma unroll
    for (int el = 0; el < 2; ++el) {
#pragma unroll
        for (int k = 0; k < 16; ++k) m1[el][k] = 0.f;
#pragma unroll
        for (int k = 0; k < 8; ++k) { m2[el][k] = 0.f; m3[el][k] = 0.f; }
#pragma unroll
        for (int k = 0; k < 4; ++k)  m4[el][k] = 0.f;
#pragma unroll
        for (int k = 0; k < 2; ++k)  m5[el][k] = 0.f;
    }

    __syncthreads();              // weights staged (also covers first sp1 write order)

    // ---- prologue: L1 for t=0 ----
    l1_step(x, 0, eglob, w1, m1, sp1, myoff, wq);
    __syncthreads();
    u32 lo[2], hi[2];
    {
        u64 v0 = *(const u64*)(sp1 + 0 * 64 + lane * 2);
        u64 v1 = *(const u64*)(sp1 + 1 * 64 + lane * 2);
        u64 v2 = *(const u64*)(sp1 + 2 * 64 + lane * 2);
        u64 v3 = *(const u64*)(sp1 + 3 * 64 + lane * 2);
        unpacki(v0 | v1, lo[0], lo[1]);   // L1 outputs 0..31 per element
        unpacki(v2 | v3, hi[0], hi[1]);   // L1 outputs 32..63 per element
    }

#pragma unroll 1
    for (int t = 0; t < T_STEPS; ++t) {
        // ================= Layer 2: 64 -> 32 (4 pairs per warp) =================
        u64 acc2[2][4];
#pragma unroll
        for (int el = 0; el < 2; ++el)
#pragma unroll
            for (int p = 0; p < 4; ++p) acc2[el][p] = 0ull;
#pragma unroll
        for (int i = 0; i < 64; ++i) {
            const ulonglong2* wp = (const ulonglong2*)(w2 + i * 4);
            ulonglong2 wa = wp[0], wb = wp[1];
            u32 bit = 1u << (i & 31);
            u64 h0 = (((i < 32) ? lo[0] : hi[0]) & bit) ? ONE2 : 0ull;
            u64 h1 = (((i < 32) ? lo[1] : hi[1]) & bit) ? ONE2 : 0ull;
            acc2[0][0] = ffma2(h0, wa.x, acc2[0][0]);
            acc2[0][1] = ffma2(h0, wa.y, acc2[0][1]);
            acc2[0][2] = ffma2(h0, wb.x, acc2[0][2]);
            acc2[0][3] = ffma2(h0, wb.y, acc2[0][3]);
            acc2[1][0] = ffma2(h1, wa.x, acc2[1][0]);
            acc2[1][1] = ffma2(h1, wa.y, acc2[1][1]);
            acc2[1][2] = ffma2(h1, wb.x, acc2[1][2]);
            acc2[1][3] = ffma2(h1, wb.y, acc2[1][3]);
        }
        {
            u32 a0 = 0, a1 = 0;
#pragma unroll
            for (int p = 0; p < 4; ++p) {
                a0 |= lif_pair(acc2[0][p], m2[0][2 * p], m2[0][2 * p + 1]) << (2 * p);
                a1 |= lif_pair(acc2[1][p], m2[1][2 * p], m2[1][2 * p + 1]) << (2 * p);
            }
            *(u64*)(sp2 + myoff) = packi(a0 << (wq * 8), a1 << (wq * 8));
        }
        __syncthreads();
        u32 f2[2];
        {
            u64 v = (*(const u64*)(sp2 + 0 * 64 + lane * 2))
                  | (*(const u64*)(sp2 + 1 * 64 + lane * 2))
                  | (*(const u64*)(sp2 + 2 * 64 + lane * 2))
                  | (*(const u64*)(sp2 + 3 * 64 + lane * 2));
            unpacki(v, f2[0], f2[1]);
        }

        // ================= Layer 3: 32 -> 32 =================
        u64 acc3[2][4];
#pragma unroll
        for (int el = 0; el < 2; ++el)
#pragma unroll
            for (int p = 0; p < 4; ++p) acc3[el][p] = 0ull;
#pragma unroll
        for (int i = 0; i < 32; ++i) {
            const ulonglong2* wp = (const ulonglong2*)(w3 + i * 4);
            ulonglong2 wa = wp[0], wb = wp[1];
            u32 bit = 1u << i;
            u64 h0 = (f2[0] & bit) ? ONE2 : 0ull;
            u64 h1 = (f2[1] & bit) ? ONE2 : 0ull;
            acc3[0][0] = ffma2(h0, wa.x, acc3[0][0]);
            acc3[0][1] = ffma2(h0, wa.y, acc3[0][1]);
            acc3[0][2] = ffma2(h0, wb.x, acc3[0][2]);
            acc3[0][3] = ffma2(h0, wb.y, acc3[0][3]);
            acc3[1][0] = ffma2(h1, wa.x, acc3[1][0]);
            acc3[1][1] = ffma2(h1, wa.y, acc3[1][1]);
            acc3[1][2] = ffma2(h1, wb.x, acc3[1][2]);
            acc3[1][3] = ffma2(h1, wb.y, acc3[1][3]);
        }
        {
            u32 a0 = 0, a1 = 0;
#pragma unroll
            for (int p = 0; p < 4; ++p) {
                a0 |= lif_pair(acc3[0][p], m3[0][2 * p], m3[0][2 * p + 1]) << (2 * p);
                a1 |= lif_pair(acc3[1][p], m3[1][2 * p], m3[1][2 * p + 1]) << (2 * p);
            }
            *(u64*)(sp3 + myoff) = packi(a0 << (wq * 8), a1 << (wq * 8));
        }
        __syncthreads();
        u32 f3[2];
        {
            u64 v = (*(const u64*)(sp3 + 0 * 64 + lane * 2))
                  | (*(const u64*)(sp3 + 1 * 64 + lane * 2))
                  | (*(const u64*)(sp3 + 2 * 64 + lane * 2))
                  | (*(const u64*)(sp3 + 3 * 64 + lane * 2));
            unpacki(v, f3[0], f3[1]);
        }

        // ================= Layer 4: 32 -> 16 (2 pairs per warp) =================
        u64 acc4[2][2];
#pragma unroll
        for (int el = 0; el < 2; ++el) { acc4[el][0] = 0ull; acc4[el][1] = 0ull; }
#pragma unroll
        for (int i = 0; i < 32; ++i) {
            const ulonglong2* wp = (const ulonglong2*)(w4 + i * 2);
            ulonglong2 wa = wp[0];
            u32 bit = 1u << i;
            u64 h0 = (f3[0] & bit) ? ONE2 : 0ull;
            u64 h1 = (f3[1] & bit) ? ONE2 : 0ull;
            acc4[0][0] = ffma2(h0, wa.x, acc4[0][0]);
            acc4[0][1] = ffma2(h0, wa.y, acc4[0][1]);
            acc4[1][0] = ffma2(h1, wa.x, acc4[1][0]);
            acc4[1][1] = ffma2(h1, wa.y, acc4[1][1]);
        }
        {
            u32 a0 = lif_pair(acc4[0][0], m4[0][0], m4[0][1])
                   | (lif_pair(acc4[0][1], m4[0][2], m4[0][3]) << 2);
            u32 a1 = lif_pair(acc4[1][0], m4[1][0], m4[1][1])
                   | (lif_pair(acc4[1][1], m4[1][2], m4[1][3]) << 2);
            *(u64*)(sp4 + myoff) = packi(a0 << (wq * 4), a1 << (wq * 4));
        }

        // ---- pipelined Layer 1 of step t+1 fills the f4-barrier shadow ----
        if (t + 1 < T_STEPS)
            l1_step(x, t + 1, eglob, w1, m1, sp1, myoff, wq);

        __syncthreads();           // releases BOTH sp4 (t) and sp1 (t+1)

        u32 f4[2];
        {
            u64 v = (*(const u64*)(sp4 + 0 * 64 + lane * 2))
                  | (*(const u64*)(sp4 + 1 * 64 + lane * 2))
                  | (*(const u64*)(sp4 + 2 * 64 + lane * 2))
                  | (*(const u64*)(sp4 + 3 * 64 + lane * 2));
            unpacki(v, f4[0], f4[1]);
        }

        // ================= Layer 5: 16 -> 6 (padded; 1 pair per warp) ============
        u64 acc5[2];
        acc5[0] = 0ull; acc5[1] = 0ull;
#pragma unroll
        for (int i = 0; i < 16; ++i) {
            u64 w = w5[i];
            u32 bit = 1u << i;
            u64 h0 = (f4[0] & bit) ? ONE2 : 0ull;
            u64 h1 = (f4[1] & bit) ? ONE2 : 0ull;
            acc5[0] = ffma2(h0, w, acc5[0]);
            acc5[1] = ffma2(h1, w, acc5[1]);
        }
#pragma unroll
        for (int el = 0; el < 2; ++el) {
            float a0, a1; unpack2(acc5[el], a0, a1);
            float r0 = m5[el][0] > THRESHF ? THRESHF : 0.0f;
            float r1 = m5[el][1] > THRESHF ? THRESHF : 0.0f;
            float mm0 = fmaf(BETAF, m5[el][0], a0 - r0);
            float mm1 = fmaf(BETAF, m5[el][1], a1 - r1);
            m5[el][0] = mm0; m5[el][1] = mm1;
            if (wq < 3) {
                float2 o;
                o.x = mm0 > THRESHF ? 1.0f : 0.0f;
                o.y = mm1 > THRESHF ? 1.0f : 0.0f;
                *(float2*)(out + ((size_t)t * BATCH + eglob + el) * 6 + wq * 2) = o;
            }
        }

        // ---- read next step's L1 masks (written before the merged barrier) ----
        if (t + 1 < T_STEPS) {
            u64 v0 = *(const u64*)(sp1 + 0 * 64 + lane * 2);
            u64 v1 = *(const u64*)(sp1 + 1 * 64 + lane * 2);
            u64 v2 = *(const u64*)(sp1 + 2 * 64 + lane * 2);
            u64 v3 = *(const u64*)(sp1 + 3 * 64 + lane * 2);
            unpacki(v0 | v1, lo[0], lo[1]);
            unpacki(v2 | v3, hi[0], hi[1]);
        }
    }
}

extern "C" void kernel_launch(void* const* d_in, const int* in_sizes, int n_in,
                              void* d_out, int out_size) {
    const float *x = nullptr, *W1 = nullptr, *W2 = nullptr, *W3 = nullptr,
                *W4 = nullptr, *W5 = nullptr;
    for (int i = 0; i < n_in; ++i) {
        const float* p = (const float*)d_in[i];
        switch (in_sizes[i]) {
            case 52428800: x  = p; break;  // (20, 262144, 10)
            case 640:      W1 = p; break;  // (64, 10)
            case 2048:     W2 = p; break;  // (32, 64)
            case 1024:     W3 = p; break;  // (32, 32)
            case 512:      W4 = p; break;  // (16, 32)
            case 96:       W5 = p; break;  // (6, 16)
            default: break;
        }
    }
    float* out = (float*)d_out;
    // 4 warps per block = 4 output-quarters; 32 lanes x E=2 -> 64 elements per block
    lif_kernel<<<BATCH / 64, 128>>>(x, W1, W2, W3, W4, W5, out);
}